// round 1
// baseline (speedup 1.0000x reference)
#include <cuda_runtime.h>
#include <mma.h>
#include <math.h>

using namespace nvcuda;

#define LSEQ 32768
#define CDIM 512
#define SCH 128
#define NCHUNK (LSEQ / SCH)   // 256
#define EPS 1e-5f

// ---------------- scratch (static device globals; no allocation) ----------------
__device__ float g_hidden[LSEQ * CDIM];
__device__ float g_u[LSEQ * CDIM];
__device__ float g_gate[LSEQ * CDIM];
__device__ float g_state[LSEQ * CDIM];
__device__ float g_x2[LSEQ * CDIM];
__device__ float g_h[LSEQ * CDIM];
__device__ float g_ff[LSEQ * 2 * CDIM];
__device__ float g_decay[CDIM];
__device__ float g_fend[NCHUNK * CDIM];
__device__ float g_bend[NCHUNK * CDIM];
__device__ float g_fcar[NCHUNK * CDIM];
__device__ float g_bcar[NCHUNK * CDIM];

// ---------------- decay = sigmoid(logit) ----------------
__global__ void decay_kernel(const float* __restrict__ logit, float* __restrict__ decay) {
    int c = threadIdx.x;
    decay[c] = 1.0f / (1.0f + expf(-logit[c]));
}

// ---------------- LayerNorm: one warp per row ----------------
__global__ void ln_kernel(const float* __restrict__ x, const float* __restrict__ w,
                          const float* __restrict__ b, float* __restrict__ out) {
    int row = blockIdx.x * blockDim.y + threadIdx.y;
    int lane = threadIdx.x;
    const float4* xr = (const float4*)(x + (size_t)row * CDIM);
    float4 v[4];
    float s = 0.f, ss = 0.f;
#pragma unroll
    for (int i = 0; i < 4; i++) {
        v[i] = xr[lane + i * 32];
        s += v[i].x + v[i].y + v[i].z + v[i].w;
        ss += v[i].x * v[i].x + v[i].y * v[i].y + v[i].z * v[i].z + v[i].w * v[i].w;
    }
#pragma unroll
    for (int off = 16; off > 0; off >>= 1) {
        s += __shfl_xor_sync(0xFFFFFFFFu, s, off);
        ss += __shfl_xor_sync(0xFFFFFFFFu, ss, off);
    }
    float mu = s * (1.0f / CDIM);
    float var = ss * (1.0f / CDIM) - mu * mu;
    float rstd = rsqrtf(var + EPS);
    const float4* w4 = (const float4*)w;
    const float4* b4 = (const float4*)b;
    float4* o4 = (float4*)(out + (size_t)row * CDIM);
#pragma unroll
    for (int i = 0; i < 4; i++) {
        int idx = lane + i * 32;
        float4 wv = w4[idx], bv = b4[idx], o;
        o.x = (v[i].x - mu) * rstd * wv.x + bv.x;
        o.y = (v[i].y - mu) * rstd * wv.y + bv.y;
        o.z = (v[i].z - mu) * rstd * wv.z + bv.z;
        o.w = (v[i].w - mu) * rstd * wv.w + bv.w;
        o4[idx] = o;
    }
}

// ---------------- TF32 wmma GEMM: C = epi(A@B + bias) [+ res] ----------------
// A: MxK row-major fp32, B: KxN row-major fp32. M%128==0, N%128==0, K%32==0.
// EPI: 0 = identity, 1 = sigmoid, 2 = silu
template <int EPI>
__global__ void gemm_kernel(const float* __restrict__ A, const float* __restrict__ B,
                            const float* __restrict__ bias, const float* __restrict__ res,
                            float* __restrict__ Cc, int M, int N, int K) {
    __shared__ float As[128][36];
    __shared__ float Bs[32][132];
    __shared__ float stage[8][256];

    int tid = threadIdx.x;
    int w = tid >> 5;
    int lane = tid & 31;
    int wr = w & 1;        // 0..1 -> 64-row slab
    int wc = w >> 1;       // 0..3 -> 32-col slab
    int rowBase = blockIdx.y * 128;
    int nBase = blockIdx.x * 128;

    wmma::fragment<wmma::accumulator, 16, 16, 8, float> acc[4][2];
#pragma unroll
    for (int i = 0; i < 4; i++)
#pragma unroll
        for (int j = 0; j < 2; j++) wmma::fill_fragment(acc[i][j], 0.0f);

    int tiles = K >> 5;
    for (int t = 0; t < tiles; t++) {
        int k0 = t << 5;
        // load A tile 128x32
#pragma unroll
        for (int p = 0; p < 4; p++) {
            int row = (tid >> 3) + p * 32;
            int c4 = (tid & 7) * 4;
            float4 v = *(const float4*)(A + (size_t)(rowBase + row) * K + k0 + c4);
            *(float4*)(&As[row][c4]) = v;
        }
        // load B tile 32x128
#pragma unroll
        for (int p = 0; p < 4; p++) {
            int kr = (tid >> 5) + p * 8;
            int c4 = (tid & 31) * 4;
            float4 v = *(const float4*)(B + (size_t)(k0 + kr) * N + nBase + c4);
            *(float4*)(&Bs[kr][c4]) = v;
        }
        __syncthreads();
#pragma unroll
        for (int kk = 0; kk < 4; kk++) {
            wmma::fragment<wmma::matrix_a, 16, 16, 8, wmma::precision::tf32, wmma::row_major> a[4];
            wmma::fragment<wmma::matrix_b, 16, 16, 8, wmma::precision::tf32, wmma::row_major> bfr[2];
#pragma unroll
            for (int i = 0; i < 4; i++) {
                wmma::load_matrix_sync(a[i], &As[wr * 64 + i * 16][kk * 8], 36);
#pragma unroll
                for (int e = 0; e < a[i].num_elements; e++) a[i].x[e] = wmma::__float_to_tf32(a[i].x[e]);
            }
#pragma unroll
            for (int j = 0; j < 2; j++) {
                wmma::load_matrix_sync(bfr[j], &Bs[kk * 8][wc * 32 + j * 16], 132);
#pragma unroll
                for (int e = 0; e < bfr[j].num_elements; e++) bfr[j].x[e] = wmma::__float_to_tf32(bfr[j].x[e]);
            }
#pragma unroll
            for (int i = 0; i < 4; i++)
#pragma unroll
                for (int j = 0; j < 2; j++)
                    wmma::mma_sync(acc[i][j], a[i], bfr[j], acc[i][j]);
        }
        __syncthreads();
    }

    // epilogue via per-warp smem staging
#pragma unroll
    for (int i = 0; i < 4; i++) {
#pragma unroll
        for (int j = 0; j < 2; j++) {
            wmma::store_matrix_sync(stage[w], acc[i][j], 16, wmma::mem_row_major);
            __syncwarp();
            int r0 = lane >> 1;
            int c0 = (lane & 1) * 8;
            size_t gr = (size_t)rowBase + wr * 64 + i * 16 + r0;
            int gcBase = nBase + wc * 32 + j * 16 + c0;
#pragma unroll
            for (int q = 0; q < 8; q++) {
                int gc = gcBase + q;
                float vv = stage[w][r0 * 16 + c0 + q] + bias[gc];
                if (EPI == 1) vv = 1.0f / (1.0f + expf(-vv));
                if (EPI == 2) vv = vv / (1.0f + expf(-vv));
                if (res) vv += res[gr * N + gc];
                Cc[gr * N + gc] = vv;
            }
            __syncwarp();
        }
    }
}

// ---------------- chunked bidirectional scan ----------------
__global__ void scan_pass1(const float* __restrict__ u, const float* __restrict__ decay,
                           float* __restrict__ fend, float* __restrict__ bend) {
    int c = threadIdx.x;
    int ch = blockIdx.x;
    float d = decay[c];
    const float* up = u + (size_t)ch * SCH * CDIM + c;
    float acc = 0.f;
#pragma unroll 8
    for (int r = 0; r < SCH; r++) acc = fmaf(d, acc, up[r * CDIM]);
    fend[ch * CDIM + c] = acc;
    acc = 0.f;
#pragma unroll 8
    for (int r = SCH - 1; r >= 0; r--) acc = fmaf(d, acc, up[r * CDIM]);
    bend[ch * CDIM + c] = acc;
}

__global__ void scan_pass2(const float* __restrict__ decay,
                           const float* __restrict__ fend, const float* __restrict__ bend,
                           float* __restrict__ fcar, float* __restrict__ bcar) {
    int c = threadIdx.x;
    float d = decay[c];
    float dS = d;
#pragma unroll
    for (int i = 0; i < 7; i++) dS = dS * dS;  // d^128
    float acc = 0.f;
#pragma unroll 4
    for (int k = 0; k < NCHUNK; k++) {
        fcar[k * CDIM + c] = acc;
        acc = fmaf(dS, acc, fend[k * CDIM + c]);
    }
    acc = 0.f;
#pragma unroll 4
    for (int k = NCHUNK - 1; k >= 0; k--) {
        bcar[k * CDIM + c] = acc;
        acc = fmaf(dS, acc, bend[k * CDIM + c]);
    }
}

__global__ void scan_pass3(const float* __restrict__ u, const float* __restrict__ gate,
                           const float* __restrict__ decay,
                           const float* __restrict__ fcar, const float* __restrict__ bcar,
                           float* __restrict__ state) {
    int c = threadIdx.x;
    int ch = blockIdx.x;
    float d = decay[c];
    size_t off = (size_t)ch * SCH * CDIM + c;
    const float* up = u + off;
    const float* gp = gate + off;
    float* sp = state + off;
    float acc = fcar[ch * CDIM + c];
#pragma unroll 8
    for (int r = 0; r < SCH; r++) {
        acc = fmaf(d, acc, up[r * CDIM]);
        sp[r * CDIM] = acc;
    }
    acc = bcar[ch * CDIM + c];
#pragma unroll 8
    for (int r = SCH - 1; r >= 0; r--) {
        acc = fmaf(d, acc, up[r * CDIM]);
        float f = sp[r * CDIM];
        sp[r * CDIM] = 0.5f * (f + acc) * gp[r * CDIM];
    }
}

// ---------------- launch ----------------
extern "C" void kernel_launch(void* const* d_in, const int* in_sizes, int n_in,
                              void* d_out, int out_size) {
    const float* x       = (const float*)d_in[0];
    const float* ln1_w   = (const float*)d_in[1];
    const float* ln1_b   = (const float*)d_in[2];
    const float* W_in    = (const float*)d_in[3];
    const float* b_in    = (const float*)d_in[4];
    const float* W_gate  = (const float*)d_in[5];
    const float* b_gate  = (const float*)d_in[6];
    const float* W_out   = (const float*)d_in[7];
    const float* b_out   = (const float*)d_in[8];
    const float* dlogit  = (const float*)d_in[9];
    const float* ln2_w   = (const float*)d_in[10];
    const float* ln2_b   = (const float*)d_in[11];
    const float* W_ff1   = (const float*)d_in[12];
    const float* b_ff1   = (const float*)d_in[13];
    const float* W_ff2   = (const float*)d_in[14];
    const float* b_ff2   = (const float*)d_in[15];
    float* out = (float*)d_out;

    float *p_hidden, *p_u, *p_gate, *p_state, *p_x2, *p_h, *p_ff, *p_decay;
    float *p_fend, *p_bend, *p_fcar, *p_bcar;
    cudaGetSymbolAddress((void**)&p_hidden, g_hidden);
    cudaGetSymbolAddress((void**)&p_u, g_u);
    cudaGetSymbolAddress((void**)&p_gate, g_gate);
    cudaGetSymbolAddress((void**)&p_state, g_state);
    cudaGetSymbolAddress((void**)&p_x2, g_x2);
    cudaGetSymbolAddress((void**)&p_h, g_h);
    cudaGetSymbolAddress((void**)&p_ff, g_ff);
    cudaGetSymbolAddress((void**)&p_decay, g_decay);
    cudaGetSymbolAddress((void**)&p_fend, g_fend);
    cudaGetSymbolAddress((void**)&p_bend, g_bend);
    cudaGetSymbolAddress((void**)&p_fcar, g_fcar);
    cudaGetSymbolAddress((void**)&p_bcar, g_bcar);

    dim3 lnBlock(32, 8);
    int lnGrid = LSEQ / 8;

    decay_kernel<<<1, CDIM>>>(dlogit, p_decay);

    // hidden = LN1(x)
    ln_kernel<<<lnGrid, lnBlock>>>(x, ln1_w, ln1_b, p_hidden);

    // u = hidden @ W_in + b_in ; gate = sigmoid(hidden @ W_gate + b_gate)
    dim3 g512(CDIM / 128, LSEQ / 128);
    gemm_kernel<0><<<g512, 256>>>(p_hidden, W_in, b_in, nullptr, p_u, LSEQ, CDIM, CDIM);
    gemm_kernel<1><<<g512, 256>>>(p_hidden, W_gate, b_gate, nullptr, p_gate, LSEQ, CDIM, CDIM);

    // bidirectional scan -> state = 0.5*(fwd+bwd)*gate
    scan_pass1<<<NCHUNK, CDIM>>>(p_u, p_decay, p_fend, p_bend);
    scan_pass2<<<1, CDIM>>>(p_decay, p_fend, p_bend, p_fcar, p_bcar);
    scan_pass3<<<NCHUNK, CDIM>>>(p_u, p_gate, p_decay, p_fcar, p_bcar, p_state);

    // x2 = x + state @ W_out + b_out
    gemm_kernel<0><<<g512, 256>>>(p_state, W_out, b_out, x, p_x2, LSEQ, CDIM, CDIM);

    // h = LN2(x2)
    ln_kernel<<<lnGrid, lnBlock>>>(p_x2, ln2_w, ln2_b, p_h);

    // ff = silu(h @ W_ff1 + b_ff1)  [N = 1024]
    dim3 g1024(2 * CDIM / 128, LSEQ / 128);
    gemm_kernel<2><<<g1024, 256>>>(p_h, W_ff1, b_ff1, nullptr, p_ff, LSEQ, 2 * CDIM, CDIM);

    // out = x2 + ff @ W_ff2 + b_ff2  [K = 1024]
    gemm_kernel<0><<<g512, 256>>>(p_ff, W_ff2, b_ff2, p_x2, out, LSEQ, CDIM, 2 * CDIM);
}

// round 3
// speedup vs baseline: 1.4492x; 1.4492x over previous
#include <cuda_runtime.h>
#include <mma.h>
#include <math.h>
#include <cstdint>

using namespace nvcuda;

#define LSEQ 32768
#define CDIM 512
#define SCH 128
#define NCHUNK (LSEQ / SCH)   // 256
#define EPS 1e-5f

#define AS_STRIDE 36
#define BS_STRIDE 132
#define EP_STRIDE 132
#define A_BYTES (128 * AS_STRIDE * 4)          // 18432
#define B_BYTES (32 * BS_STRIDE * 4)           // 16896
#define STG_BYTES (A_BYTES + B_BYTES)          // 35328
#define SMEM_TOTAL (2 * STG_BYTES)             // 70656 (>= 128*132*4 epilogue)

// ---------------- scratch (static device globals; no allocation) ----------------
__device__ float g_hidden[LSEQ * CDIM];
__device__ float g_u[LSEQ * CDIM];
__device__ float g_gate[LSEQ * CDIM];
__device__ float g_state[LSEQ * CDIM];
__device__ float g_x2[LSEQ * CDIM];
__device__ float g_h[LSEQ * CDIM];
__device__ float g_ff[LSEQ * 2 * CDIM];
__device__ float g_decay[CDIM];
__device__ float g_fend[NCHUNK * CDIM];
__device__ float g_bend[NCHUNK * CDIM];
__device__ float g_fcar[NCHUNK * CDIM];
__device__ float g_bcar[NCHUNK * CDIM];

__device__ __forceinline__ uint32_t smem_u32(const void* p) {
    uint32_t a;
    asm("{ .reg .u64 t; cvta.to.shared.u64 t, %1; cvt.u32.u64 %0, t; }" : "=r"(a) : "l"(p));
    return a;
}

#define CP_ASYNC16(dst_u32, gptr) \
    asm volatile("cp.async.cg.shared.global [%0], [%1], 16;" :: "r"(dst_u32), "l"(gptr))
#define CP_COMMIT() asm volatile("cp.async.commit_group;" ::: "memory")
#define CP_WAIT(n)  asm volatile("cp.async.wait_group %0;" :: "n"(n) : "memory")

// ---------------- decay = sigmoid(logit) ----------------
__global__ void decay_kernel(const float* __restrict__ logit, float* __restrict__ decay) {
    int c = threadIdx.x;
    decay[c] = 1.0f / (1.0f + expf(-logit[c]));
}

// ---------------- LayerNorm: one warp per row ----------------
__global__ void ln_kernel(const float* __restrict__ x, const float* __restrict__ w,
                          const float* __restrict__ b, float* __restrict__ out) {
    int row = blockIdx.x * blockDim.y + threadIdx.y;
    int lane = threadIdx.x;
    const float4* xr = (const float4*)(x + (size_t)row * CDIM);
    float4 v[4];
    float s = 0.f, ss = 0.f;
#pragma unroll
    for (int i = 0; i < 4; i++) {
        v[i] = xr[lane + i * 32];
        s += v[i].x + v[i].y + v[i].z + v[i].w;
        ss += v[i].x * v[i].x + v[i].y * v[i].y + v[i].z * v[i].z + v[i].w * v[i].w;
    }
#pragma unroll
    for (int off = 16; off > 0; off >>= 1) {
        s += __shfl_xor_sync(0xFFFFFFFFu, s, off);
        ss += __shfl_xor_sync(0xFFFFFFFFu, ss, off);
    }
    float mu = s * (1.0f / CDIM);
    float var = ss * (1.0f / CDIM) - mu * mu;
    float rstd = rsqrtf(var + EPS);
    const float4* w4 = (const float4*)w;
    const float4* b4 = (const float4*)b;
    float4* o4 = (float4*)(out + (size_t)row * CDIM);
#pragma unroll
    for (int i = 0; i < 4; i++) {
        int idx = lane + i * 32;
        float4 wv = w4[idx], bv = b4[idx], o;
        o.x = (v[i].x - mu) * rstd * wv.x + bv.x;
        o.y = (v[i].y - mu) * rstd * wv.y + bv.y;
        o.z = (v[i].z - mu) * rstd * wv.z + bv.z;
        o.w = (v[i].w - mu) * rstd * wv.w + bv.w;
        o4[idx] = o;
    }
}

// ---------------- TF32 wmma GEMM, cp.async double-buffered ----------------
// C = epi(A@B + bias) [+ res].  A: MxK fp32 row-major, B: KxN fp32 row-major.
// EPI: 0 = identity, 1 = sigmoid, 2 = silu
template <int EPI>
__global__ void __launch_bounds__(256)
gemm_kernel(const float* __restrict__ A, const float* __restrict__ B,
            const float* __restrict__ bias, const float* __restrict__ res,
            float* __restrict__ Cc, int M, int N, int K) {
    extern __shared__ char smem[];
    uint32_t sb = smem_u32(smem);

    int tid = threadIdx.x;
    int w = tid >> 5;
    int wr = w & 1;        // 0..1 -> 64-row slab
    int wc = w >> 1;       // 0..3 -> 32-col slab
    int rowBase = blockIdx.y * 128;
    int nBase = blockIdx.x * 128;

    wmma::fragment<wmma::accumulator, 16, 16, 8, float> acc[4][2];
#pragma unroll
    for (int i = 0; i < 4; i++)
#pragma unroll
        for (int j = 0; j < 2; j++) wmma::fill_fragment(acc[i][j], 0.0f);

    const int T = K >> 5;

    // stage loader: A tile 128x32 (stride 36), B tile 32x128 (stride 132)
    auto load_stage = [&](int t, int s) {
        int k0 = t << 5;
        uint32_t abase = sb + s * STG_BYTES;
        uint32_t bbase = abase + A_BYTES;
#pragma unroll
        for (int p = 0; p < 4; p++) {
            int idx = tid + 256 * p;
            int row = idx >> 3;
            int c4 = (idx & 7) * 4;
            CP_ASYNC16(abase + (uint32_t)(row * AS_STRIDE + c4) * 4,
                       A + (size_t)(rowBase + row) * K + k0 + c4);
        }
#pragma unroll
        for (int p = 0; p < 4; p++) {
            int idx = tid + 256 * p;
            int kr = idx >> 5;
            int c4 = (idx & 31) * 4;
            CP_ASYNC16(bbase + (uint32_t)(kr * BS_STRIDE + c4) * 4,
                       B + (size_t)(k0 + kr) * N + nBase + c4);
        }
    };

    load_stage(0, 0);
    CP_COMMIT();

    for (int t = 0; t < T; t++) {
        int s = t & 1;
        if (t + 1 < T) {
            load_stage(t + 1, s ^ 1);
            CP_COMMIT();
            CP_WAIT(1);
        } else {
            CP_WAIT(0);
        }
        __syncthreads();

        const float* As = (const float*)(smem + s * STG_BYTES);
        const float* Bs = (const float*)(smem + s * STG_BYTES + A_BYTES);
#pragma unroll
        for (int kk = 0; kk < 4; kk++) {
            wmma::fragment<wmma::matrix_a, 16, 16, 8, wmma::precision::tf32, wmma::row_major> a[4];
            wmma::fragment<wmma::matrix_b, 16, 16, 8, wmma::precision::tf32, wmma::row_major> bfr[2];
#pragma unroll
            for (int i = 0; i < 4; i++) {
                wmma::load_matrix_sync(a[i], As + (wr * 64 + i * 16) * AS_STRIDE + kk * 8, AS_STRIDE);
#pragma unroll
                for (int e = 0; e < a[i].num_elements; e++) a[i].x[e] = wmma::__float_to_tf32(a[i].x[e]);
            }
#pragma unroll
            for (int j = 0; j < 2; j++) {
                wmma::load_matrix_sync(bfr[j], Bs + (kk * 8) * BS_STRIDE + wc * 32 + j * 16, BS_STRIDE);
#pragma unroll
                for (int e = 0; e < bfr[j].num_elements; e++) bfr[j].x[e] = wmma::__float_to_tf32(bfr[j].x[e]);
            }
#pragma unroll
            for (int i = 0; i < 4; i++)
#pragma unroll
                for (int j = 0; j < 2; j++)
                    wmma::mma_sync(acc[i][j], a[i], bfr[j], acc[i][j]);
        }
        __syncthreads();
    }

    // ---- epilogue: stage whole 128x128 tile in smem, one vectorized pass ----
    float* ep = (float*)smem;
#pragma unroll
    for (int i = 0; i < 4; i++)
#pragma unroll
        for (int j = 0; j < 2; j++)
            wmma::store_matrix_sync(ep + (size_t)(wr * 64 + i * 16) * EP_STRIDE + wc * 32 + j * 16,
                                    acc[i][j], EP_STRIDE, wmma::mem_row_major);
    __syncthreads();

#pragma unroll
    for (int p = 0; p < 16; p++) {
        int idx = tid + 256 * p;          // 4096 float4 = 128 rows x 32 float4
        int row = idx >> 5;
        int c4 = (idx & 31) * 4;
        float4 v = *(float4*)(ep + (size_t)row * EP_STRIDE + c4);
        float4 bv = *(const float4*)(bias + nBase + c4);
        v.x += bv.x; v.y += bv.y; v.z += bv.z; v.w += bv.w;
        if (EPI == 1) {
            v.x = 1.0f / (1.0f + expf(-v.x)); v.y = 1.0f / (1.0f + expf(-v.y));
            v.z = 1.0f / (1.0f + expf(-v.z)); v.w = 1.0f / (1.0f + expf(-v.w));
        }
        if (EPI == 2) {
            v.x = v.x / (1.0f + expf(-v.x)); v.y = v.y / (1.0f + expf(-v.y));
            v.z = v.z / (1.0f + expf(-v.z)); v.w = v.w / (1.0f + expf(-v.w));
        }
        size_t goff = (size_t)(rowBase + row) * N + nBase + c4;
        if (res) {
            float4 rv = *(const float4*)(res + goff);
            v.x += rv.x; v.y += rv.y; v.z += rv.z; v.w += rv.w;
        }
        *(float4*)(Cc + goff) = v;
    }
}

// ---------------- chunked bidirectional scan ----------------
__global__ void scan_pass1(const float* __restrict__ u, const float* __restrict__ decay,
                           float* __restrict__ fend, float* __restrict__ bend) {
    int c = threadIdx.x;
    int ch = blockIdx.x;
    float d = decay[c];
    const float* up = u + (size_t)ch * SCH * CDIM + c;
    float acc = 0.f;
#pragma unroll 8
    for (int r = 0; r < SCH; r++) acc = fmaf(d, acc, up[r * CDIM]);
    fend[ch * CDIM + c] = acc;
    acc = 0.f;
#pragma unroll 8
    for (int r = SCH - 1; r >= 0; r--) acc = fmaf(d, acc, up[r * CDIM]);
    bend[ch * CDIM + c] = acc;
}

__global__ void scan_pass2(const float* __restrict__ decay,
                           const float* __restrict__ fend, const float* __restrict__ bend,
                           float* __restrict__ fcar, float* __restrict__ bcar) {
    int c = threadIdx.x;
    float d = decay[c];
    float dS = d;
#pragma unroll
    for (int i = 0; i < 7; i++) dS = dS * dS;  // d^128
    float acc = 0.f;
#pragma unroll 4
    for (int k = 0; k < NCHUNK; k++) {
        fcar[k * CDIM + c] = acc;
        acc = fmaf(dS, acc, fend[k * CDIM + c]);
    }
    acc = 0.f;
#pragma unroll 4
    for (int k = NCHUNK - 1; k >= 0; k--) {
        bcar[k * CDIM + c] = acc;
        acc = fmaf(dS, acc, bend[k * CDIM + c]);
    }
}

__global__ void scan_pass3(const float* __restrict__ u, const float* __restrict__ gate,
                           const float* __restrict__ decay,
                           const float* __restrict__ fcar, const float* __restrict__ bcar,
                           float* __restrict__ state) {
    int c = threadIdx.x;
    int ch = blockIdx.x;
    float d = decay[c];
    size_t off = (size_t)ch * SCH * CDIM + c;
    const float* up = u + off;
    const float* gp = gate + off;
    float* sp = state + off;
    float acc = fcar[ch * CDIM + c];
#pragma unroll 8
    for (int r = 0; r < SCH; r++) {
        acc = fmaf(d, acc, up[r * CDIM]);
        sp[r * CDIM] = acc;
    }
    acc = bcar[ch * CDIM + c];
#pragma unroll 8
    for (int r = SCH - 1; r >= 0; r--) {
        acc = fmaf(d, acc, up[r * CDIM]);
        float f = sp[r * CDIM];
        sp[r * CDIM] = 0.5f * (f + acc) * gp[r * CDIM];
    }
}

// ---------------- launch ----------------
extern "C" void kernel_launch(void* const* d_in, const int* in_sizes, int n_in,
                              void* d_out, int out_size) {
    const float* x       = (const float*)d_in[0];
    const float* ln1_w   = (const float*)d_in[1];
    const float* ln1_b   = (const float*)d_in[2];
    const float* W_in    = (const float*)d_in[3];
    const float* b_in    = (const float*)d_in[4];
    const float* W_gate  = (const float*)d_in[5];
    const float* b_gate  = (const float*)d_in[6];
    const float* W_out   = (const float*)d_in[7];
    const float* b_out   = (const float*)d_in[8];
    const float* dlogit  = (const float*)d_in[9];
    const float* ln2_w   = (const float*)d_in[10];
    const float* ln2_b   = (const float*)d_in[11];
    const float* W_ff1   = (const float*)d_in[12];
    const float* b_ff1   = (const float*)d_in[13];
    const float* W_ff2   = (const float*)d_in[14];
    const float* b_ff2   = (const float*)d_in[15];
    float* out = (float*)d_out;

    float *p_hidden, *p_u, *p_gate, *p_state, *p_x2, *p_h, *p_ff, *p_decay;
    float *p_fend, *p_bend, *p_fcar, *p_bcar;
    cudaGetSymbolAddress((void**)&p_hidden, g_hidden);
    cudaGetSymbolAddress((void**)&p_u, g_u);
    cudaGetSymbolAddress((void**)&p_gate, g_gate);
    cudaGetSymbolAddress((void**)&p_state, g_state);
    cudaGetSymbolAddress((void**)&p_x2, g_x2);
    cudaGetSymbolAddress((void**)&p_h, g_h);
    cudaGetSymbolAddress((void**)&p_ff, g_ff);
    cudaGetSymbolAddress((void**)&p_decay, g_decay);
    cudaGetSymbolAddress((void**)&p_fend, g_fend);
    cudaGetSymbolAddress((void**)&p_bend, g_bend);
    cudaGetSymbolAddress((void**)&p_fcar, g_fcar);
    cudaGetSymbolAddress((void**)&p_bcar, g_bcar);

    cudaFuncSetAttribute(gemm_kernel<0>, cudaFuncAttributeMaxDynamicSharedMemorySize, SMEM_TOTAL);
    cudaFuncSetAttribute(gemm_kernel<1>, cudaFuncAttributeMaxDynamicSharedMemorySize, SMEM_TOTAL);
    cudaFuncSetAttribute(gemm_kernel<2>, cudaFuncAttributeMaxDynamicSharedMemorySize, SMEM_TOTAL);

    dim3 lnBlock(32, 8);
    int lnGrid = LSEQ / 8;

    decay_kernel<<<1, CDIM>>>(dlogit, p_decay);

    // hidden = LN1(x)
    ln_kernel<<<lnGrid, lnBlock>>>(x, ln1_w, ln1_b, p_hidden);

    // u = hidden @ W_in + b_in ; gate = sigmoid(hidden @ W_gate + b_gate)
    dim3 g512(CDIM / 128, LSEQ / 128);
    gemm_kernel<0><<<g512, 256, SMEM_TOTAL>>>(p_hidden, W_in, b_in, nullptr, p_u, LSEQ, CDIM, CDIM);
    gemm_kernel<1><<<g512, 256, SMEM_TOTAL>>>(p_hidden, W_gate, b_gate, nullptr, p_gate, LSEQ, CDIM, CDIM);

    // bidirectional scan -> state = 0.5*(fwd+bwd)*gate
    scan_pass1<<<NCHUNK, CDIM>>>(p_u, p_decay, p_fend, p_bend);
    scan_pass2<<<1, CDIM>>>(p_decay, p_fend, p_bend, p_fcar, p_bcar);
    scan_pass3<<<NCHUNK, CDIM>>>(p_u, p_gate, p_decay, p_fcar, p_bcar, p_state);

    // x2 = x + state @ W_out + b_out
    gemm_kernel<0><<<g512, 256, SMEM_TOTAL>>>(p_state, W_out, b_out, x, p_x2, LSEQ, CDIM, CDIM);

    // h = LN2(x2)
    ln_kernel<<<lnGrid, lnBlock>>>(p_x2, ln2_w, ln2_b, p_h);

    // ff = silu(h @ W_ff1 + b_ff1)  [N = 1024]
    dim3 g1024(2 * CDIM / 128, LSEQ / 128);
    gemm_kernel<2><<<g1024, 256, SMEM_TOTAL>>>(p_h, W_ff1, b_ff1, nullptr, p_ff, LSEQ, 2 * CDIM, CDIM);

    // out = x2 + ff @ W_ff2 + b_ff2  [K = 1024]
    gemm_kernel<0><<<g512, 256, SMEM_TOTAL>>>(p_ff, W_ff2, b_ff2, p_x2, out, LSEQ, CDIM, 2 * CDIM);
}